// round 14
// baseline (speedup 1.0000x reference)
#include <cuda_runtime.h>

constexpr int NMAX  = 100000;
constexpr int D_IN  = 16;
constexpr int D_HID = 32;
constexpr int D_OUT = 16;

#define PACK_F32X2(out, lo, hi) \
    asm("mov.b64 %0, {%1, %2};" : "=l"(out) : "f"(lo), "f"(hi))
#define UNPACK_F32X2(lo, hi, in) \
    asm("mov.b64 {%0, %1}, %2;" : "=f"(lo), "=f"(hi) : "l"(in))
#define FMA_F32X2(d, a, b, c) \
    asm("fma.rn.f32x2 %0, %1, %2, %3;" : "=l"(d) : "l"(a), "l"(b), "l"(c))

// Scratch (__device__ globals; allocation-free rule). Zero-initialized at load.
__device__ alignas(16) float g_pre [NMAX * D_IN];
__device__ alignas(16) float g_agg1[NMAX * D_IN];
__device__ alignas(16) float g_hs2 [NMAX * D_OUT];
__device__ alignas(16) float g_agg2[NMAX * D_OUT];
__device__ float g_dinv[NMAX];
__device__ int   g_deg [NMAX];    // 0 at entry; reset in pre phase each call
__device__ unsigned g_bar_count;  // barrier arrivals (returns to 0 each barrier)
__device__ unsigned g_bar_gen;    // barrier generation (monotonic; re-entrant)

// Software grid barrier. ALL blocks must be co-resident (grid sized by
// occupancy query on the host). Sense = generation word.
__device__ __forceinline__ void gbar(unsigned nb) {
    __syncthreads();
    if (threadIdx.x == 0) {
        __threadfence();                       // release my phase's writes
        unsigned my = *(volatile unsigned*)&g_bar_gen;
        if (atomicAdd(&g_bar_count, 1u) == nb - 1) {
            g_bar_count = 0;
            __threadfence();
            *(volatile unsigned*)&g_bar_gen = my + 1;
        } else {
            while (*(volatile unsigned*)&g_bar_gen == my) { }
        }
        __threadfence();                       // acquire others' writes
    }
    __syncthreads();
}

__global__ void __launch_bounds__(256, 3) k_all(
    const int* __restrict__ x, const int* __restrict__ ei,
    const float* __restrict__ emb,
    const float* __restrict__ W1, const float* __restrict__ b1,
    const float* __restrict__ W2, const float* __restrict__ b2,
    float* __restrict__ out, int n, int E, unsigned nb)
{
    // Stage weights once (f32x2-packed; LDS.128 reads later). Valid for the
    // whole kernel. First use is in the mid phase, well past several
    // __syncthreads-bearing barriers.
    __shared__ ulonglong2 W1s[D_IN * D_HID / 4];       // 128
    __shared__ ulonglong2 W2s[D_HID * D_OUT / 4];      // 128
    __shared__ unsigned long long b1s[D_HID / 2];      // 16
    for (int t = threadIdx.x; t < D_IN * D_HID / 4; t += 256)
        W1s[t] = reinterpret_cast<const ulonglong2*>(W1)[t];
    for (int t = threadIdx.x; t < D_HID * D_OUT / 4; t += 256)
        W2s[t] = reinterpret_cast<const ulonglong2*>(W2)[t];
    if (threadIdx.x < D_HID / 2)
        b1s[threadIdx.x] = reinterpret_cast<const unsigned long long*>(b1)[threadIdx.x];

    const int T   = (int)gridDim.x * 256;
    const int tid = (int)blockIdx.x * 256 + threadIdx.x;
    const int* src = ei;
    const int* dst = ei + E;

    // ---- Phase 1: degree histogram (int4 over dst) -------------------------
    for (int e4 = tid * 4; e4 < E; e4 += T * 4) {
        if (e4 + 3 < E) {
            int4 d = *reinterpret_cast<const int4*>(dst + e4);
            atomicAdd(&g_deg[d.x], 1); atomicAdd(&g_deg[d.y], 1);
            atomicAdd(&g_deg[d.z], 1); atomicAdd(&g_deg[d.w], 1);
        } else {
            for (int e = e4; e < E; e++) atomicAdd(&g_deg[dst[e]], 1);
        }
    }
    gbar(nb);

    // ---- Phase 2: pre = emb[x[v]]*dinv; agg1 seed; deg reset ---------------
    // 4 lanes per node, convergent at the g_deg load -> read-before-reset ok.
    for (int t = tid; t < n * 4; t += T) {
        int v = t >> 2, q = t & 3;
        int d = g_deg[v];
        float dinv = rsqrtf((float)(d + 1));
        if (q == 0) { g_deg[v] = 0; g_dinv[v] = dinv; }
        int xr = __ldg(&x[v]);
        float4 e = __ldg(reinterpret_cast<const float4*>(emb) + (size_t)xr * 4 + q);
        float4 p = make_float4(e.x * dinv, e.y * dinv, e.z * dinv, e.w * dinv);
        reinterpret_cast<float4*>(g_pre )[(size_t)v * 4 + q] = p;
        reinterpret_cast<float4*>(g_agg1)[(size_t)v * 4 + q] = p;
    }
    gbar(nb);

    // ---- Phase 3: scatter1 (red.v4 in 16-dim space) ------------------------
    for (long long t = tid; t < (long long)E * 4; t += T) {
        int e = (int)(t >> 2), c = (int)t & 3;
        int s = __ldg(&src[e]);
        int d = __ldg(&dst[e]);
        float4 v = __ldg(reinterpret_cast<const float4*>(g_pre + ((size_t)s << 4)) + c);
        float* p = g_agg1 + ((size_t)d << 4) + c * 4;
        asm volatile("red.global.add.v4.f32 [%0], {%1,%2,%3,%4};"
                     :: "l"(p), "f"(v.x), "f"(v.y), "f"(v.z), "f"(v.w) : "memory");
    }
    gbar(nb);

    // ---- Phase 4: mid (thread/node, f32x2 math). agg1 read via __ldcg ------
    for (int v = tid; v < n; v += T) {
        float dinv = g_dinv[v];
        float a[D_IN];
        const float4* ar = reinterpret_cast<const float4*>(g_agg1 + (size_t)v * D_IN);
#pragma unroll
        for (int q = 0; q < 4; q++) {
            float4 t4 = __ldcg(ar + q);            // bypass L1 (red-modified)
            a[q*4+0] = t4.x * dinv; a[q*4+1] = t4.y * dinv;
            a[q*4+2] = t4.z * dinv; a[q*4+3] = t4.w * dinv;
        }

        unsigned long long r2[D_HID / 2];
#pragma unroll
        for (int j2 = 0; j2 < D_HID / 2; j2++) r2[j2] = b1s[j2];
#pragma unroll
        for (int k = 0; k < D_IN; k++) {
            unsigned long long ap;
            PACK_F32X2(ap, a[k], a[k]);
#pragma unroll
            for (int j4 = 0; j4 < D_HID / 4; j4++) {
                ulonglong2 w = W1s[k * (D_HID / 4) + j4];
                FMA_F32X2(r2[2*j4+0], ap, w.x, r2[2*j4+0]);
                FMA_F32X2(r2[2*j4+1], ap, w.y, r2[2*j4+1]);
            }
        }
        float r[D_HID];
#pragma unroll
        for (int j2 = 0; j2 < D_HID / 2; j2++) {
            float lo, hi;
            UNPACK_F32X2(lo, hi, r2[j2]);
            r[2*j2+0] = fmaxf(lo, 0.f);
            r[2*j2+1] = fmaxf(hi, 0.f);
        }

        unsigned long long h2[D_OUT / 2];
#pragma unroll
        for (int j2 = 0; j2 < D_OUT / 2; j2++) h2[j2] = 0ull;
#pragma unroll
        for (int k = 0; k < D_HID; k++) {
            unsigned long long rp;
            PACK_F32X2(rp, r[k], r[k]);
#pragma unroll
            for (int j4 = 0; j4 < D_OUT / 4; j4++) {
                ulonglong2 w = W2s[k * (D_OUT / 4) + j4];
                FMA_F32X2(h2[2*j4+0], rp, w.x, h2[2*j4+0]);
                FMA_F32X2(h2[2*j4+1], rp, w.y, h2[2*j4+1]);
            }
        }
        float h[D_OUT];
#pragma unroll
        for (int j2 = 0; j2 < D_OUT / 2; j2++) {
            float lo, hi;
            UNPACK_F32X2(lo, hi, h2[j2]);
            h[2*j2+0] = lo * dinv;
            h[2*j2+1] = hi * dinv;
        }
        float4* hr = reinterpret_cast<float4*>(g_hs2  + (size_t)v * D_OUT);
        float4* gr = reinterpret_cast<float4*>(g_agg2 + (size_t)v * D_OUT);
#pragma unroll
        for (int q = 0; q < 4; q++) {
            float4 t4 = make_float4(h[q*4+0], h[q*4+1], h[q*4+2], h[q*4+3]);
            hr[q] = t4;
            gr[q] = t4;
        }
    }
    gbar(nb);

    // ---- Phase 5: scatter2 -------------------------------------------------
    for (long long t = tid; t < (long long)E * 4; t += T) {
        int e = (int)(t >> 2), c = (int)t & 3;
        int s = __ldg(&src[e]);
        int d = __ldg(&dst[e]);
        float4 v = __ldcg(reinterpret_cast<const float4*>(g_hs2 + ((size_t)s << 4)) + c);
        float* p = g_agg2 + ((size_t)d << 4) + c * 4;
        asm volatile("red.global.add.v4.f32 [%0], {%1,%2,%3,%4};"
                     :: "l"(p), "f"(v.x), "f"(v.y), "f"(v.z), "f"(v.w) : "memory");
    }
    gbar(nb);

    // ---- Phase 6: post = agg2*dinv + b2 -> out -----------------------------
    for (int t = tid; t < n * 4; t += T) {
        int v = t >> 2, q = t & 3;
        float dinv = g_dinv[v];
        float4 a = __ldcg(reinterpret_cast<const float4*>(g_agg2) + (size_t)v * 4 + q);
        float4 bb = __ldg(reinterpret_cast<const float4*>(b2) + q);
        reinterpret_cast<float4*>(out)[(size_t)v * 4 + q] =
            make_float4(dinv * a.x + bb.x, dinv * a.y + bb.y,
                        dinv * a.z + bb.z, dinv * a.w + bb.w);
    }
}

extern "C" void kernel_launch(void* const* d_in, const int* in_sizes, int n_in,
                              void* d_out, int out_size) {
    const int*   x   = (const int*)  d_in[0];
    const int*   ei  = (const int*)  d_in[1];   // [2, E]: src then dst
    const float* emb = (const float*)d_in[2];
    const float* W1  = (const float*)d_in[3];
    const float* b1  = (const float*)d_in[4];
    const float* W2  = (const float*)d_in[5];
    const float* b2  = (const float*)d_in[6];
    float* out = (float*)d_out;

    int n = in_sizes[0];
    int E = in_sizes[1] / 2;

    // Co-residency sizing: grid = SMs * occupancy (host queries; no allocs).
    int sms = 148;
    cudaDeviceGetAttribute(&sms, cudaDevAttrMultiProcessorCount, 0);
    int maxb = 0;
    cudaOccupancyMaxActiveBlocksPerMultiprocessor(&maxb, k_all, 256, 0);
    if (maxb < 1) maxb = 1;
    if (maxb > 4) maxb = 4;
    unsigned nb = (unsigned)(sms * maxb);

    k_all<<<nb, 256>>>(x, ei, emb, W1, b1, W2, b2, out, n, E, nb);
}

// round 16
// speedup vs baseline: 1.0787x; 1.0787x over previous
#include <cuda_runtime.h>

constexpr int NMAX  = 100000;
constexpr int D_IN  = 16;
constexpr int D_HID = 32;
constexpr int D_OUT = 16;

// Scratch (__device__ globals; allocation-free rule). Zero-initialized at load.
__device__ alignas(16) float g_pre [NMAX * D_IN];   // emb[x[v]] * dinv[v]
__device__ alignas(16) float g_agg1[NMAX * D_IN];   // self + Sum over in-edges
__device__ alignas(16) float g_r   [NMAX * D_HID];  // relu(a@W1 + b1)
__device__ alignas(16) float g_hs2 [NMAX * D_OUT];  // (r@W2) * dinv
__device__ alignas(16) float g_agg2[NMAX * D_OUT];  // self + Sum over in-edges
__device__ float g_dinv[NMAX];
__device__ int   g_deg [NMAX];   // 0 at entry (static init / reset by k_pre)

// ---------------------------------------------------------------------------
// K1: degree histogram over real edges (self-loop folded as +1 in k_pre).
__global__ void k_deg(const int* __restrict__ dst, int E) {
    int i = blockIdx.x * blockDim.x + threadIdx.x;
    int e4 = i * 4;
    if (e4 + 3 < E) {
        int4 d = *reinterpret_cast<const int4*>(dst + e4);
        atomicAdd(&g_deg[d.x], 1); atomicAdd(&g_deg[d.y], 1);
        atomicAdd(&g_deg[d.z], 1); atomicAdd(&g_deg[d.w], 1);
    } else {
        for (int e = e4; e < E && e >= 0; e++) atomicAdd(&g_deg[dst[e]], 1);
    }
}

// K2: 4 threads per node: dinv; pre = emb[x[v]]*dinv; agg1 = pre (self seed);
//     deg reset. Node's 4 threads are warp-contiguous and convergent at the
//     load, so read-before-lane0-reset is race-free.
__global__ void k_pre(const int* __restrict__ x, const float* __restrict__ emb,
                      int n) {
    int t = blockIdx.x * blockDim.x + threadIdx.x;
    int v = t >> 2, q = t & 3;
    if (v >= n) return;
    int d = g_deg[v];
    float dinv = rsqrtf((float)(d + 1));
    if (q == 0) { g_deg[v] = 0; g_dinv[v] = dinv; }
    int xr = __ldg(&x[v]);
    float4 e = reinterpret_cast<const float4*>(emb)[(size_t)xr * 4 + q];
    float4 p = make_float4(e.x * dinv, e.y * dinv, e.z * dinv, e.w * dinv);
    reinterpret_cast<float4*>(g_pre )[(size_t)v * 4 + q] = p;
    reinterpret_cast<float4*>(g_agg1)[(size_t)v * 4 + q] = p;
}

// K3/K6: edge scatter in 16-dim space: 4 threads per edge, red.v4 per thread.
template <int LAYER>
__global__ void k_scatter(const int* __restrict__ src, const int* __restrict__ dst,
                          int E) {
    const float* in  = (LAYER == 1) ? g_pre  : g_hs2;
    float*       out = (LAYER == 1) ? g_agg1 : g_agg2;

    long long t = (long long)blockIdx.x * blockDim.x + threadIdx.x;
    int e = (int)(t >> 2);
    if (e >= E) return;
    int c = (int)t & 3;

    int s = __ldg(&src[e]);
    int d = __ldg(&dst[e]);

    float4 v = *reinterpret_cast<const float4*>(in + ((size_t)s << 4) + c * 4);
    float* p = out + ((size_t)d << 4) + c * 4;
    asm volatile("red.global.add.v4.f32 [%0], {%1,%2,%3,%4};"
                 :: "l"(p), "f"(v.x), "f"(v.y), "f"(v.z), "f"(v.w) : "memory");
}

// K4: midA — 4 threads per node, lane q owns W1 columns [8q, 8q+8).
//     r[8q..8q+8) = relu(b1 + (agg1*dinv) @ W1). 128 FMA, no exchange.
__global__ void k_midA(const float* __restrict__ W1, const float* __restrict__ b1,
                       int n) {
    __shared__ float4 W1s[D_IN * D_HID / 4];   // [k][j4] 16 x 8
    __shared__ float  b1s[D_HID];
    for (int t = threadIdx.x; t < D_IN * D_HID / 4; t += blockDim.x)
        W1s[t] = reinterpret_cast<const float4*>(W1)[t];
    if (threadIdx.x < D_HID) b1s[threadIdx.x] = b1[threadIdx.x];
    __syncthreads();

    int t = blockIdx.x * blockDim.x + threadIdx.x;
    int v = t >> 2, q = t & 3;
    if (v >= n) return;

    float dinv = g_dinv[v];
    float a[D_IN];
    const float4* ar = reinterpret_cast<const float4*>(g_agg1 + (size_t)v * D_IN);
#pragma unroll
    for (int c = 0; c < 4; c++) {
        float4 t4 = ar[c];
        a[c*4+0] = t4.x * dinv; a[c*4+1] = t4.y * dinv;
        a[c*4+2] = t4.z * dinv; a[c*4+3] = t4.w * dinv;
    }

    float r[8];
#pragma unroll
    for (int i = 0; i < 8; i++) r[i] = b1s[q * 8 + i];
#pragma unroll
    for (int k = 0; k < D_IN; k++) {
        float ak = a[k];
        float4 w0 = W1s[k * (D_HID / 4) + 2 * q];
        float4 w1 = W1s[k * (D_HID / 4) + 2 * q + 1];
        r[0] = fmaf(ak, w0.x, r[0]); r[1] = fmaf(ak, w0.y, r[1]);
        r[2] = fmaf(ak, w0.z, r[2]); r[3] = fmaf(ak, w0.w, r[3]);
        r[4] = fmaf(ak, w1.x, r[4]); r[5] = fmaf(ak, w1.y, r[5]);
        r[6] = fmaf(ak, w1.z, r[6]); r[7] = fmaf(ak, w1.w, r[7]);
    }
    float4* rr = reinterpret_cast<float4*>(g_r + (size_t)v * D_HID + q * 8);
    rr[0] = make_float4(fmaxf(r[0], 0.f), fmaxf(r[1], 0.f),
                        fmaxf(r[2], 0.f), fmaxf(r[3], 0.f));
    rr[1] = make_float4(fmaxf(r[4], 0.f), fmaxf(r[5], 0.f),
                        fmaxf(r[6], 0.f), fmaxf(r[7], 0.f));
}

// K5: midB — 4 threads per node, lane q owns W2 output cols [4q, 4q+4).
//     hs2 = agg2 = dinv * (r @ W2)[4q..4q+4). 128 FMA, no exchange.
__global__ void k_midB(const float* __restrict__ W2, int n) {
    __shared__ float4 W2s[D_HID * D_OUT / 4];  // [k][j4] 32 x 4
    for (int t = threadIdx.x; t < D_HID * D_OUT / 4; t += blockDim.x)
        W2s[t] = reinterpret_cast<const float4*>(W2)[t];
    __syncthreads();

    int t = blockIdx.x * blockDim.x + threadIdx.x;
    int v = t >> 2, q = t & 3;
    if (v >= n) return;

    float dinv = g_dinv[v];
    float h0 = 0.f, h1 = 0.f, h2 = 0.f, h3 = 0.f;
    const float4* rr = reinterpret_cast<const float4*>(g_r + (size_t)v * D_HID);
#pragma unroll
    for (int k4 = 0; k4 < D_HID / 4; k4++) {
        float4 rv = rr[k4];
        float4 w;
        w = W2s[(4 * k4 + 0) * (D_OUT / 4) + q];
        h0 = fmaf(rv.x, w.x, h0); h1 = fmaf(rv.x, w.y, h1);
        h2 = fmaf(rv.x, w.z, h2); h3 = fmaf(rv.x, w.w, h3);
        w = W2s[(4 * k4 + 1) * (D_OUT / 4) + q];
        h0 = fmaf(rv.y, w.x, h0); h1 = fmaf(rv.y, w.y, h1);
        h2 = fmaf(rv.y, w.z, h2); h3 = fmaf(rv.y, w.w, h3);
        w = W2s[(4 * k4 + 2) * (D_OUT / 4) + q];
        h0 = fmaf(rv.z, w.x, h0); h1 = fmaf(rv.z, w.y, h1);
        h2 = fmaf(rv.z, w.z, h2); h3 = fmaf(rv.z, w.w, h3);
        w = W2s[(4 * k4 + 3) * (D_OUT / 4) + q];
        h0 = fmaf(rv.w, w.x, h0); h1 = fmaf(rv.w, w.y, h1);
        h2 = fmaf(rv.w, w.z, h2); h3 = fmaf(rv.w, w.w, h3);
    }
    float4 hv = make_float4(h0 * dinv, h1 * dinv, h2 * dinv, h3 * dinv);
    reinterpret_cast<float4*>(g_hs2 )[(size_t)v * 4 + q] = hv;
    reinterpret_cast<float4*>(g_agg2)[(size_t)v * 4 + q] = hv;
}

// K7: 4 threads per node: out = agg2*dinv + b2.
__global__ void k_post(const float* __restrict__ b2, float* __restrict__ out, int n) {
    int t = blockIdx.x * blockDim.x + threadIdx.x;
    int v = t >> 2, q = t & 3;
    if (v >= n) return;
    float dinv = g_dinv[v];
    float4 a = reinterpret_cast<const float4*>(g_agg2)[(size_t)v * 4 + q];
    float4 bb = __ldg(reinterpret_cast<const float4*>(b2) + q);
    reinterpret_cast<float4*>(out)[(size_t)v * 4 + q] =
        make_float4(dinv * a.x + bb.x, dinv * a.y + bb.y,
                    dinv * a.z + bb.z, dinv * a.w + bb.w);
}

extern "C" void kernel_launch(void* const* d_in, const int* in_sizes, int n_in,
                              void* d_out, int out_size) {
    const int*   x   = (const int*)  d_in[0];
    const int*   ei  = (const int*)  d_in[1];   // [2, E]: src then dst
    const float* emb = (const float*)d_in[2];
    const float* W1  = (const float*)d_in[3];
    const float* b1  = (const float*)d_in[4];
    const float* W2  = (const float*)d_in[5];
    const float* b2  = (const float*)d_in[6];
    float* out = (float*)d_out;

    int n = in_sizes[0];
    int E = in_sizes[1] / 2;
    const int* src = ei;
    const int* dst = ei + E;

    const int B = 256;
    long long et = (long long)E * 4;
    int nb_edge  = (int)((et + B - 1) / B);
    int nb_node4 = (n * 4 + B - 1) / B;

    k_deg       <<<(E / 4 + B - 1) / B + 1, B>>>(dst, E);
    k_pre       <<<nb_node4, B>>>(x, emb, n);
    k_scatter<1><<<nb_edge, B>>>(src, dst, E);
    k_midA      <<<nb_node4, B>>>(W1, b1, n);
    k_midB      <<<nb_node4, B>>>(W2, n);
    k_scatter<2><<<nb_edge, B>>>(src, dst, E);
    k_post      <<<nb_node4, B>>>(b2, out, n);
}

// round 17
// speedup vs baseline: 1.2815x; 1.1879x over previous
#include <cuda_runtime.h>

constexpr int NMAX  = 100000;
constexpr int EMAX  = 1600000;
constexpr int D_IN  = 16;
constexpr int D_HID = 32;
constexpr int D_OUT = 16;

#define PACK_F32X2(out, lo, hi) \
    asm("mov.b64 %0, {%1, %2};" : "=l"(out) : "f"(lo), "f"(hi))
#define UNPACK_F32X2(lo, hi, in) \
    asm("mov.b64 {%0, %1}, %2;" : "=f"(lo), "=f"(hi) : "l"(in))
#define FMA_F32X2(d, a, b, c) \
    asm("fma.rn.f32x2 %0, %1, %2, %3;" : "=l"(d) : "l"(a), "l"(b), "l"(c))

// Scratch (__device__ globals; allocation-free rule). Zero-initialized at load.
__device__ alignas(16) float g_pre[NMAX * D_IN];   // emb[x[v]] * dinv[v]
__device__ alignas(16) float g_a  [NMAX * D_IN];   // dinv*(sum + self)  (conv1 pre-GEMM)
__device__ alignas(16) float g_hs2[NMAX * D_OUT];  // (relu(a@W1+b1)@W2) * dinv
__device__ float g_dinv[NMAX];
__device__ int   g_deg [NMAX];   // 0 at entry (static init / reset by k_build)
__device__ int   g_row [NMAX];   // CSR bucket start (by dst)
__device__ int   g_cur [NMAX];   // fill cursor; == bucket end after k_fill
__device__ int   g_csr [EMAX];   // src per CSR slot
__device__ int   g_ctr;          // bucket allocator (reset by k_deg)

// ---------------------------------------------------------------------------
// K1: degree histogram over real edges; resets bucket allocator.
__global__ void k_deg(const int* __restrict__ dst, int E) {
    if (blockIdx.x == 0 && threadIdx.x == 0) g_ctr = 0;
    int i = blockIdx.x * blockDim.x + threadIdx.x;
    int e4 = i * 4;
    if (e4 + 3 < E) {
        int4 d = *reinterpret_cast<const int4*>(dst + e4);
        atomicAdd(&g_deg[d.x], 1); atomicAdd(&g_deg[d.y], 1);
        atomicAdd(&g_deg[d.z], 1); atomicAdd(&g_deg[d.w], 1);
    } else {
        for (int e = e4; e < E && e >= 0; e++) atomicAdd(&g_deg[dst[e]], 1);
    }
}

// K2: per block: smem scan of 256 degrees + ONE atomicAdd for the block base
//     (cross-block bucket order irrelevant; only disjointness matters).
//     Also: dinv, pre = emb[x[v]]*dinv, deg reset.
__global__ void k_build(const int* __restrict__ x, const float* __restrict__ emb,
                        int n) {
    __shared__ int sm[256];
    __shared__ int base_s;
    int v = blockIdx.x * 256 + threadIdx.x;
    int d = (v < n) ? g_deg[v] : 0;

    sm[threadIdx.x] = d;
    __syncthreads();
#pragma unroll
    for (int o = 1; o < 256; o <<= 1) {
        int t = (threadIdx.x >= o) ? sm[threadIdx.x - o] : 0;
        __syncthreads();
        sm[threadIdx.x] += t;
        __syncthreads();
    }
    int incl = sm[threadIdx.x];
    if (threadIdx.x == 255) base_s = atomicAdd(&g_ctr, incl);
    __syncthreads();

    if (v < n) {
        int start = base_s + incl - d;
        g_row[v] = start;
        g_cur[v] = start;
        g_deg[v] = 0;                          // reset for next replay
        float dinv = rsqrtf((float)(d + 1));   // +1 self-loop
        g_dinv[v] = dinv;
        int xr = __ldg(&x[v]);
        const float4* er = reinterpret_cast<const float4*>(emb) + (size_t)xr * 4;
        float4* pr = reinterpret_cast<float4*>(g_pre) + (size_t)v * 4;
#pragma unroll
        for (int q = 0; q < 4; q++) {
            float4 e = er[q];
            pr[q] = make_float4(e.x * dinv, e.y * dinv, e.z * dinv, e.w * dinv);
        }
    }
}

// K3: bucket fill: csr[pos] = src for each edge, bucketed by dst.
__global__ void k_fill(const int* __restrict__ src, const int* __restrict__ dst,
                       int E) {
    int e = blockIdx.x * blockDim.x + threadIdx.x;
    if (e >= E) return;
    int d = __ldg(&dst[e]);
    int pos = atomicAdd(&g_cur[d], 1);
    g_csr[pos] = __ldg(&src[e]);
}

// K4/K6: gather aggregation, 8 threads per node: chunk = lane&3 (one float4
//     of the 64B row -> 4 lanes share a 128B line: low wavefront count),
//     sub = lane>>2 & 1 (2 neighbors in flight). One xor-4 reduce round.
//     LAYER 1: g_a = dinv*(sum + pre[v]).
//     LAYER 2: out = dinv*(sum + hs2[v]) + b2.
template <int LAYER>
__global__ void k_gather(const float* __restrict__ b2, float* __restrict__ out,
                         int n) {
    const float* in = (LAYER == 1) ? g_pre : g_hs2;

    int t = blockIdx.x * blockDim.x + threadIdx.x;
    int v = t >> 3;
    if (v >= n) return;
    int chunk = t & 3;
    int sub   = (t >> 2) & 1;

    int j = g_row[v] + sub, end = g_cur[v];
    float4 acc = make_float4(0.f, 0.f, 0.f, 0.f);
    for (; j < end; j += 2) {
        int s = __ldg(&g_csr[j]);
        float4 w = reinterpret_cast<const float4*>(in)[(size_t)s * 4 + chunk];
        acc.x += w.x; acc.y += w.y; acc.z += w.z; acc.w += w.w;
    }
    acc.x += __shfl_xor_sync(~0u, acc.x, 4);
    acc.y += __shfl_xor_sync(~0u, acc.y, 4);
    acc.z += __shfl_xor_sync(~0u, acc.z, 4);
    acc.w += __shfl_xor_sync(~0u, acc.w, 4);

    if (sub == 0) {
        float dinv = g_dinv[v];
        float4 self = reinterpret_cast<const float4*>(in)[(size_t)v * 4 + chunk];
        if (LAYER == 1) {
            reinterpret_cast<float4*>(g_a)[(size_t)v * 4 + chunk] =
                make_float4(dinv * (acc.x + self.x), dinv * (acc.y + self.y),
                            dinv * (acc.z + self.z), dinv * (acc.w + self.w));
        } else {
            float4 bb = __ldg(reinterpret_cast<const float4*>(b2) + chunk);
            reinterpret_cast<float4*>(out)[(size_t)v * 4 + chunk] =
                make_float4(dinv * (acc.x + self.x) + bb.x,
                            dinv * (acc.y + self.y) + bb.y,
                            dinv * (acc.z + self.z) + bb.z,
                            dinv * (acc.w + self.w) + bb.w);
        }
    }
}

// K5: thread per node (R13-measured best). Weights in shared as packed
//     f32-pairs via LDS.128; math via fma.rn.f32x2. Input g_a pre-normalized.
//     hs2 = (relu(a@W1+b1)@W2) * dinv.
__global__ void k_mid(const float* __restrict__ W1, const float* __restrict__ b1,
                      const float* __restrict__ W2, int n) {
    __shared__ ulonglong2 W1s[D_IN * D_HID / 4];       // 128
    __shared__ ulonglong2 W2s[D_HID * D_OUT / 4];      // 128
    __shared__ unsigned long long b1s[D_HID / 2];      // 16
    for (int t = threadIdx.x; t < D_IN * D_HID / 4; t += blockDim.x)
        W1s[t] = reinterpret_cast<const ulonglong2*>(W1)[t];
    for (int t = threadIdx.x; t < D_HID * D_OUT / 4; t += blockDim.x)
        W2s[t] = reinterpret_cast<const ulonglong2*>(W2)[t];
    if (threadIdx.x < D_HID / 2)
        b1s[threadIdx.x] = reinterpret_cast<const unsigned long long*>(b1)[threadIdx.x];
    __syncthreads();

    int v = blockIdx.x * blockDim.x + threadIdx.x;
    if (v >= n) return;

    float dinv = g_dinv[v];
    float a[D_IN];
    const float4* ar = reinterpret_cast<const float4*>(g_a + (size_t)v * D_IN);
#pragma unroll
    for (int q = 0; q < D_IN / 4; q++) {
        float4 t = ar[q];
        a[q*4+0] = t.x; a[q*4+1] = t.y; a[q*4+2] = t.z; a[q*4+3] = t.w;
    }

    unsigned long long r2[D_HID / 2];
#pragma unroll
    for (int j2 = 0; j2 < D_HID / 2; j2++) r2[j2] = b1s[j2];
#pragma unroll
    for (int k = 0; k < D_IN; k++) {
        unsigned long long ap;
        PACK_F32X2(ap, a[k], a[k]);
#pragma unroll
        for (int j4 = 0; j4 < D_HID / 4; j4++) {
            ulonglong2 w = W1s[k * (D_HID / 4) + j4];
            FMA_F32X2(r2[2*j4+0], ap, w.x, r2[2*j4+0]);
            FMA_F32X2(r2[2*j4+1], ap, w.y, r2[2*j4+1]);
        }
    }
    float r[D_HID];
#pragma unroll
    for (int j2 = 0; j2 < D_HID / 2; j2++) {
        float lo, hi;
        UNPACK_F32X2(lo, hi, r2[j2]);
        r[2*j2+0] = fmaxf(lo, 0.f);
        r[2*j2+1] = fmaxf(hi, 0.f);
    }

    unsigned long long h2[D_OUT / 2];
#pragma unroll
    for (int j2 = 0; j2 < D_OUT / 2; j2++) h2[j2] = 0ull;
#pragma unroll
    for (int k = 0; k < D_HID; k++) {
        unsigned long long rp;
        PACK_F32X2(rp, r[k], r[k]);
#pragma unroll
        for (int j4 = 0; j4 < D_OUT / 4; j4++) {
            ulonglong2 w = W2s[k * (D_OUT / 4) + j4];
            FMA_F32X2(h2[2*j4+0], rp, w.x, h2[2*j4+0]);
            FMA_F32X2(h2[2*j4+1], rp, w.y, h2[2*j4+1]);
        }
    }

    float h[D_OUT];
#pragma unroll
    for (int j2 = 0; j2 < D_OUT / 2; j2++) {
        float lo, hi;
        UNPACK_F32X2(lo, hi, h2[j2]);
        h[2*j2+0] = lo * dinv;
        h[2*j2+1] = hi * dinv;
    }

    float4* hr = reinterpret_cast<float4*>(g_hs2 + (size_t)v * D_OUT);
#pragma unroll
    for (int q = 0; q < D_OUT / 4; q++)
        hr[q] = make_float4(h[q*4+0], h[q*4+1], h[q*4+2], h[q*4+3]);
}

extern "C" void kernel_launch(void* const* d_in, const int* in_sizes, int n_in,
                              void* d_out, int out_size) {
    const int*   x   = (const int*)  d_in[0];
    const int*   ei  = (const int*)  d_in[1];   // [2, E]: src then dst
    const float* emb = (const float*)d_in[2];
    const float* W1  = (const float*)d_in[3];
    const float* b1  = (const float*)d_in[4];
    const float* W2  = (const float*)d_in[5];
    const float* b2  = (const float*)d_in[6];
    float* out = (float*)d_out;

    int n = in_sizes[0];
    int E = in_sizes[1] / 2;
    const int* src = ei;
    const int* dst = ei + E;

    const int B = 256;
    int nb_node8 = (n * 8 + B - 1) / B;

    k_deg      <<<(E / 4 + B - 1) / B + 1, B>>>(dst, E);
    k_build    <<<(n + 255) / 256, 256>>>(x, emb, n);
    k_fill     <<<(E + B - 1) / B, B>>>(src, dst, E);
    k_gather<1><<<nb_node8, B>>>(nullptr, nullptr, n);
    k_mid      <<<(n + 127) / 128, 128>>>(W1, b1, W2, n);
    k_gather<2><<<nb_node8, B>>>(b2, out, n);
}